// round 7
// baseline (speedup 1.0000x reference)
#include <cuda_runtime.h>
#include <math.h>

// ---------------- problem constants ----------------
#define NTREES   32
#define NPG      4095
#define NTOT     (NTREES * NPG)      // 131040
#define EDIM     256
#define HDIM     256
#define IOUD     768
#define CDIM     104
#define VOCABSZ  20000
#define PADTOK   (VOCABSZ - 1)       // 19999

// ---------------- scratch (device globals; no allocations allowed) ----------------
__device__ float g_tab  [(size_t)VOCABSZ * IOUD];         // emb @ W_iou^T + b_iou  (61.4 MB)
__device__ float g_h    [(size_t)NTOT * HDIM];            // hidden states
__device__ float g_c    [(size_t)NTOT * HDIM];            // cell states
__device__ float g_htild[(size_t)NTREES * 1024 * HDIM];   // segment sum of child h
__device__ float g_cagg [(size_t)NTREES * 1024 * HDIM];   // segment sum of f * child c
__device__ float g_uadd [(size_t)NTREES * 1024 * IOUD];   // htild @ U_iou^T per level

__device__ __forceinline__ float sigf(float v) { return 1.f / (1.f + __expf(-v)); }

// ============================================================================
// Kernel 1: vocab table GEMM.  g_tab[v][j] = dot(emb[v], W_iou[j]) + b_iou[j]
// (emb row for PAD token treated as zero, per reference emb.at[PAD].set(0))
// Tile: 64x64, BK=16, 256 threads, 4x4 micro-tile.
// ============================================================================
__global__ __launch_bounds__(256) void tab_kernel(
    const float* __restrict__ emb,    // [VOCAB, 256]
    const float* __restrict__ W,      // [768, 256]
    const float* __restrict__ bias)   // [768]
{
    __shared__ float As[16][68];
    __shared__ float Bs[16][68];
    int m0 = blockIdx.x * 64, n0 = blockIdx.y * 64;
    int tid = threadIdx.x;
    int tx = tid & 15, ty = tid >> 4;
    int lm = tid >> 2, lk = (tid & 3) * 4;

    float acc[4][4] = {};
    int arow_idx = m0 + lm;
    bool aval = (arow_idx < VOCABSZ) && (arow_idx != PADTOK);
    const float* arow = emb + (size_t)arow_idx * EDIM + lk;
    const float* brow = W + (size_t)(n0 + lm) * EDIM + lk;

    for (int k0 = 0; k0 < EDIM; k0 += 16) {
        float4 av = aval ? *(const float4*)(arow + k0) : make_float4(0.f, 0.f, 0.f, 0.f);
        As[lk + 0][lm] = av.x; As[lk + 1][lm] = av.y; As[lk + 2][lm] = av.z; As[lk + 3][lm] = av.w;
        float4 bv = *(const float4*)(brow + k0);
        Bs[lk + 0][lm] = bv.x; Bs[lk + 1][lm] = bv.y; Bs[lk + 2][lm] = bv.z; Bs[lk + 3][lm] = bv.w;
        __syncthreads();
#pragma unroll
        for (int kk = 0; kk < 16; ++kk) {
            float4 a4 = *(const float4*)&As[kk][ty * 4];
            float4 b4 = *(const float4*)&Bs[kk][tx * 4];
            float ar[4] = {a4.x, a4.y, a4.z, a4.w};
            float br[4] = {b4.x, b4.y, b4.z, b4.w};
#pragma unroll
            for (int i = 0; i < 4; ++i)
#pragma unroll
                for (int j = 0; j < 4; ++j) acc[i][j] += ar[i] * br[j];
        }
        __syncthreads();
    }
    float bb[4];
#pragma unroll
    for (int j = 0; j < 4; ++j) bb[j] = bias[n0 + tx * 4 + j];
#pragma unroll
    for (int i = 0; i < 4; ++i) {
        int r = m0 + ty * 4 + i;
        if (r < VOCABSZ) {
            float* o = g_tab + (size_t)r * IOUD + n0 + tx * 4;
#pragma unroll
            for (int j = 0; j < 4; ++j) o[j] = acc[i][j] + bb[j];
        }
    }
}

// ============================================================================
// Kernel 2: forget gate GEMM + segment scatter for children of one level.
// Rows = children at level d+1 (M = B * 2^(d+1)).
// f = sigmoid(h_child @ U_f_w^T + U_f_b); atomicAdd htild[slot] += h_child,
// cagg[slot] += f * c_child, where slot is the parent's slot at level d.
// ============================================================================
__global__ __launch_bounds__(256) void f_scatter_kernel(
    const int* __restrict__ par,
    const float* __restrict__ Uf,    // [256, 256]
    const float* __restrict__ Ufb,   // [256]
    int childStart, int ncShift, int parStart, int nd, int M)
{
    __shared__ float As[16][68];
    __shared__ float Bs[16][68];
    __shared__ int nodeb[64];
    __shared__ int slotb[64];

    int m0 = blockIdx.x * 64, n0 = blockIdx.y * 64;
    int tid = threadIdx.x;
    int tx = tid & 15, ty = tid >> 4;
    int lm = tid >> 2, lk = (tid & 3) * 4;

    if (tid < 64) {
        int r = m0 + tid;
        int node = -1, slot = 0;
        if (r < M) {
            int g = r >> ncShift;
            int i = r & ((1 << ncShift) - 1);
            node = g * NPG + childStart + i;
            int p = par[node];
            int g2 = p / NPG;
            slot = g2 * nd + (p - g2 * NPG - parStart);
        }
        nodeb[tid] = node;
        slotb[tid] = slot;
    }
    __syncthreads();

    float acc[4][4] = {};
    int mynode = nodeb[lm];
    const float* arow = (mynode >= 0) ? (g_h + (size_t)mynode * HDIM + lk) : nullptr;
    const float* brow = Uf + (size_t)(n0 + lm) * HDIM + lk;

    for (int k0 = 0; k0 < HDIM; k0 += 16) {
        float4 av = arow ? *(const float4*)(arow + k0) : make_float4(0.f, 0.f, 0.f, 0.f);
        As[lk + 0][lm] = av.x; As[lk + 1][lm] = av.y; As[lk + 2][lm] = av.z; As[lk + 3][lm] = av.w;
        float4 bv = *(const float4*)(brow + k0);
        Bs[lk + 0][lm] = bv.x; Bs[lk + 1][lm] = bv.y; Bs[lk + 2][lm] = bv.z; Bs[lk + 3][lm] = bv.w;
        __syncthreads();
#pragma unroll
        for (int kk = 0; kk < 16; ++kk) {
            float4 a4 = *(const float4*)&As[kk][ty * 4];
            float4 b4 = *(const float4*)&Bs[kk][tx * 4];
            float ar[4] = {a4.x, a4.y, a4.z, a4.w};
            float br[4] = {b4.x, b4.y, b4.z, b4.w};
#pragma unroll
            for (int i = 0; i < 4; ++i)
#pragma unroll
                for (int j = 0; j < 4; ++j) acc[i][j] += ar[i] * br[j];
        }
        __syncthreads();
    }

    float bb[4];
#pragma unroll
    for (int j = 0; j < 4; ++j) bb[j] = Ufb[n0 + tx * 4 + j];

#pragma unroll
    for (int i = 0; i < 4; ++i) {
        int rr = m0 + ty * 4 + i;
        if (rr >= M) continue;
        int node = nodeb[ty * 4 + i];
        int slot = slotb[ty * 4 + i];
        const float* hrow = g_h + (size_t)node * HDIM;
        const float* crow = g_c + (size_t)node * HDIM;
        float* caggrow = g_cagg + (size_t)slot * HDIM;
        float* htrow = g_htild + (size_t)slot * HDIM;
#pragma unroll
        for (int j = 0; j < 4; ++j) {
            int col = n0 + tx * 4 + j;
            float f = sigf(acc[i][j] + bb[j]);
            atomicAdd(caggrow + col, f * crow[col]);
            atomicAdd(htrow + col, hrow[col]);
        }
    }
}

// ============================================================================
// Kernel 3: g_uadd[r] = g_htild[r] @ U_iou^T for parents at level d (M rows).
// ============================================================================
__global__ __launch_bounds__(256) void uiou_kernel(
    const float* __restrict__ U,   // [768, 256]
    int M)
{
    __shared__ float As[16][68];
    __shared__ float Bs[16][68];
    int m0 = blockIdx.x * 64, n0 = blockIdx.y * 64;
    int tid = threadIdx.x;
    int tx = tid & 15, ty = tid >> 4;
    int lm = tid >> 2, lk = (tid & 3) * 4;

    float acc[4][4] = {};
    bool aval = (m0 + lm) < M;
    const float* arow = g_htild + (size_t)(m0 + lm) * HDIM + lk;
    const float* brow = U + (size_t)(n0 + lm) * HDIM + lk;

    for (int k0 = 0; k0 < HDIM; k0 += 16) {
        float4 av = aval ? *(const float4*)(arow + k0) : make_float4(0.f, 0.f, 0.f, 0.f);
        As[lk + 0][lm] = av.x; As[lk + 1][lm] = av.y; As[lk + 2][lm] = av.z; As[lk + 3][lm] = av.w;
        float4 bv = *(const float4*)(brow + k0);
        Bs[lk + 0][lm] = bv.x; Bs[lk + 1][lm] = bv.y; Bs[lk + 2][lm] = bv.z; Bs[lk + 3][lm] = bv.w;
        __syncthreads();
#pragma unroll
        for (int kk = 0; kk < 16; ++kk) {
            float4 a4 = *(const float4*)&As[kk][ty * 4];
            float4 b4 = *(const float4*)&Bs[kk][tx * 4];
            float ar[4] = {a4.x, a4.y, a4.z, a4.w};
            float br[4] = {b4.x, b4.y, b4.z, b4.w};
#pragma unroll
            for (int i = 0; i < 4; ++i)
#pragma unroll
                for (int j = 0; j < 4; ++j) acc[i][j] += ar[i] * br[j];
        }
        __syncthreads();
    }
#pragma unroll
    for (int i = 0; i < 4; ++i) {
        int rr = m0 + ty * 4 + i;
        if (rr < M) {
            float* o = g_uadd + (size_t)rr * IOUD + n0 + tx * 4;
#pragma unroll
            for (int j = 0; j < 4; ++j) o[j] = acc[i][j];
        }
    }
}

// ============================================================================
// Kernel 4: gates for level d.  One block per node row (M blocks, 256 threads).
// iou row = g_tab[x[node]] (+ g_uadd[r] if non-leaf); c = sig(i)*tanh(u)+cagg;
// h = sig(o)*tanh(c).
// ============================================================================
__global__ __launch_bounds__(256) void gates_kernel(
    const int* __restrict__ x, int nodeStart, int ndShift, int hasChild)
{
    int r = blockIdx.x;
    int j = threadIdx.x;
    int g = r >> ndShift;
    int node = g * NPG + nodeStart + (r & ((1 << ndShift) - 1));
    int xv = __ldg(x + node);
    const float* trow = g_tab + (size_t)xv * IOUD;
    float iv = trow[j];
    float ov = trow[256 + j];
    float uv = trow[512 + j];
    float cn;
    if (hasChild) {
        const float* ua = g_uadd + (size_t)r * IOUD;
        iv += ua[j]; ov += ua[256 + j]; uv += ua[512 + j];
        cn = sigf(iv) * tanhf(uv) + g_cagg[(size_t)r * HDIM + j];
    } else {
        cn = sigf(iv) * tanhf(uv);
    }
    g_c[(size_t)node * HDIM + j] = cn;
    g_h[(size_t)node * HDIM + j] = sigf(ov) * tanhf(cn);
}

// ============================================================================
// Kernel 5: zero the segment accumulators for one level (n elements each).
// ============================================================================
__global__ void zero_hc(int n)
{
    int i = blockIdx.x * blockDim.x + threadIdx.x;
    if (i < n) { g_htild[i] = 0.f; g_cagg[i] = 0.f; }
}

// ============================================================================
// Kernel 6: classifier.  out[g][c] = dot(h[root_g], lin_w[c]) + lin_b[c].
// One block per tree; 8 warps, warp w handles classes w, w+8, ...
// ============================================================================
__global__ __launch_bounds__(256) void classify_kernel(
    const float* __restrict__ lin_w,  // [104, 256]
    const float* __restrict__ lin_b,  // [104]
    float* __restrict__ out)          // [32, 104]
{
    int g = blockIdx.x;
    const float* hr = g_h + (size_t)g * NPG * HDIM;   // root node = g*NPG
    int warp = threadIdx.x >> 5, lane = threadIdx.x & 31;
    for (int cc = warp; cc < CDIM; cc += 8) {
        const float* w = lin_w + (size_t)cc * HDIM;
        float s = 0.f;
#pragma unroll
        for (int k = lane; k < HDIM; k += 32) s += hr[k] * w[k];
#pragma unroll
        for (int off = 16; off; off >>= 1) s += __shfl_xor_sync(0xffffffffu, s, off);
        if (lane == 0) out[g * CDIM + cc] = s + lin_b[cc];
    }
}

// ============================================================================
// Host
// ============================================================================
extern "C" void kernel_launch(void* const* d_in, const int* in_sizes, int n_in,
                              void* d_out, int out_size)
{
    const int*   x      = (const int*)  d_in[0];
    const int*   par    = (const int*)  d_in[1];
    const float* emb    = (const float*)d_in[2];
    const float* W_iou  = (const float*)d_in[3];
    const float* U_iou  = (const float*)d_in[4];
    const float* b_iou  = (const float*)d_in[5];
    const float* U_f_w  = (const float*)d_in[6];
    const float* U_f_b  = (const float*)d_in[7];
    const float* lin_w  = (const float*)d_in[8];
    const float* lin_b  = (const float*)d_in[9];
    float* out = (float*)d_out;

    static const int STARTS_H[12] = {0, 1, 3, 7, 15, 31, 63, 127, 255, 511, 1023, 2047};

    // Phase 1: vocab table (emb @ W_iou^T + b_iou) — 20000 rows instead of 131040
    {
        dim3 grid((VOCABSZ + 63) / 64, IOUD / 64);
        tab_kernel<<<grid, 256>>>(emb, W_iou, b_iou);
    }

    // Phase 2: topological sweep, leaves (d=11) -> root (d=0)
    for (int d = 11; d >= 0; --d) {
        int nd = 1 << d;
        int M = NTREES * nd;            // parents at this level
        if (d < 11) {
            int Mc = NTREES * (nd << 1); // children at level d+1
            int zn = M * HDIM;
            zero_hc<<<(zn + 255) / 256, 256>>>(zn);
            dim3 gf((Mc + 63) / 64, HDIM / 64);
            f_scatter_kernel<<<gf, 256>>>(par, U_f_w, U_f_b,
                                          STARTS_H[d + 1], d + 1, STARTS_H[d], nd, Mc);
            dim3 gu((M + 63) / 64, IOUD / 64);
            uiou_kernel<<<gu, 256>>>(U_iou, M);
        }
        gates_kernel<<<M, 256>>>(x, STARTS_H[d], d, d < 11 ? 1 : 0);
    }

    // Phase 3: classifier on the 32 roots
    classify_kernel<<<NTREES, 256>>>(lin_w, lin_b, out);
}